// round 6
// baseline (speedup 1.0000x reference)
#include <cuda_runtime.h>
#include <cuda_bf16.h>
#include <math.h>
#include <cstdint>

// Problem constants
#define BATCH 8
#define LEN   2048
#define DIM   1024
#define DFF   4096
#define NFFT  4096
#define LN_EPS 1e-5f
#define WFS   2064        // half-spectrum row stride

// ---------------------------------------------------------------------------
// Static device scratch (no allocation allowed)
// ---------------------------------------------------------------------------
__device__ float  g_lnz  [BATCH * LEN * DIM];
__device__ float  g_lnzT [BATCH * DIM * LEN];
__device__ float  g_hfilt[LEN * DIM];
__device__ float  g_hfiltT[DIM * LEN];
__device__ float  g_hidT [DIM * LEN];
__device__ float2 g_wfh  [DIM * WFS];
__device__ float2 g_twd  [1024];
__device__ float  g_znewT[BATCH * DIM * LEN];
__device__ float  g_znew [BATCH * LEN * DIM];
__device__ __nv_bfloat16 g_Xh[BATCH * LEN * DIM];
__device__ __nv_bfloat16 g_Xl[BATCH * LEN * DIM];
__device__ __nv_bfloat16 g_Hh[BATCH * LEN * DFF];
__device__ __nv_bfloat16 g_Hl[BATCH * LEN * DFF];
__device__ __nv_bfloat16 g_posh[LEN * DIM];
__device__ __nv_bfloat16 g_posl[LEN * DIM];
__device__ __nv_bfloat16 g_wp1t_h[DFF * DIM];
__device__ __nv_bfloat16 g_wp1t_l[DFF * DIM];
__device__ __nv_bfloat16 g_wp2t_h[DIM * DFF];
__device__ __nv_bfloat16 g_wp2t_l[DIM * DFF];
__device__ __nv_bfloat16 g_w1t_h[DFF * DIM];
__device__ __nv_bfloat16 g_w1t_l[DFF * DIM];
__device__ __nv_bfloat16 g_w2t_h[DIM * DFF];
__device__ __nv_bfloat16 g_w2t_l[DIM * DFF];

// ---------------------------------------------------------------------------
// PTX wrappers (baseline sm_80+ only)
// ---------------------------------------------------------------------------
__device__ __forceinline__ uint32_t smem_u32(const void* p) {
    uint32_t a;
    asm("{ .reg .u64 t; cvta.to.shared.u64 t, %1; cvt.u32.u64 %0, t; }"
        : "=r"(a) : "l"(p));
    return a;
}
__device__ __forceinline__ void cpasync16(uint32_t s, const void* g) {
    asm volatile("cp.async.cg.shared.global [%0], [%1], 16;"
                 :: "r"(s), "l"(g) : "memory");
}
__device__ __forceinline__ void cp_commit() {
    asm volatile("cp.async.commit_group;" ::: "memory");
}
template <int N>
__device__ __forceinline__ void cp_wait() {
    asm volatile("cp.async.wait_group %0;" :: "n"(N) : "memory");
}
__device__ __forceinline__ void ldm_x4(uint32_t& r0, uint32_t& r1,
                                       uint32_t& r2, uint32_t& r3, uint32_t a) {
    asm volatile("ldmatrix.sync.aligned.m8n8.x4.shared.b16 {%0,%1,%2,%3}, [%4];"
                 : "=r"(r0), "=r"(r1), "=r"(r2), "=r"(r3) : "r"(a));
}
__device__ __forceinline__ void mma_bf16(float4& d, const uint32_t* a,
                                         uint32_t b0, uint32_t b1) {
    asm volatile(
        "mma.sync.aligned.m16n8k16.row.col.f32.bf16.bf16.f32 "
        "{%0,%1,%2,%3}, {%4,%5,%6,%7}, {%8,%9}, {%0,%1,%2,%3};"
        : "+f"(d.x), "+f"(d.y), "+f"(d.z), "+f"(d.w)
        : "r"(a[0]), "r"(a[1]), "r"(a[2]), "r"(a[3]), "r"(b0), "r"(b1));
}

// ---------------------------------------------------------------------------
// HMMA GEMM: C[M,N] = epi( (Ah+Al)[M,K] @ (Bh+Bl)[N,K]^T + bias )
// Block 128x256, BK=32, 8 warps (2m x 4n), warp tile 64x64,
// 3-stage cp.async pipeline, 80B-padded rows, split-bf16 3-term product.
// ---------------------------------------------------------------------------
#define GBM 128
#define GBN 256
#define GBK 32
// per-stage layout (bytes):
//   Ah @ 0      : 128 rows * 80B = 10240
//   Al @ 10240
//   Bh @ 20480  : 256 rows * 80B = 20480
//   Bl @ 40960
#define A_MAT 10240
#define B_OFF 20480
#define B_MAT 20480
#define STAGE_B 61440
#define GEMM_SMEM (3 * STAGE_B)      // 184320 bytes

template <int ACT, bool SPLIT_OUT, bool HAS_ADD>
__global__ __launch_bounds__(256)
void gemm_mma(const __nv_bfloat16* __restrict__ Ah, const __nv_bfloat16* __restrict__ Al,
              const __nv_bfloat16* __restrict__ Bh, const __nv_bfloat16* __restrict__ Bl,
              const float* __restrict__ bias, const float* __restrict__ add,
              float* __restrict__ Cf, __nv_bfloat16* __restrict__ Ch,
              __nv_bfloat16* __restrict__ Cl, int M, int N, int K) {
    extern __shared__ char smem[];
    const uint32_t sbase = smem_u32(smem);
    const int tid  = threadIdx.x;
    const int lane = tid & 31;
    const int wid  = tid >> 5;
    const int wm   = wid & 1;        // 2 warp rows (64 M each)
    const int wn   = wid >> 1;       // 4 warp cols (64 N each)
    const int bm = blockIdx.y * GBM;
    const int bn = blockIdx.x * GBN;

    // gmem staging coords: thread -> row r0 (0..63), 16B chunk c0 (0..3)
    const int r0 = tid >> 2;
    const int c0 = tid & 3;
    const uint32_t soA0 = (uint32_t)(r0 * 80 + c0 * 16);
    const uint32_t soA1 = (uint32_t)((r0 + 64) * 80 + c0 * 16);

    auto issue_loads = [&](int stage, int k0) {
        const uint32_t sb = sbase + stage * STAGE_B;
        const size_t kk = (size_t)k0 + c0 * 8;
        // A (128 rows)
        cpasync16(sb + soA0,         Ah + (size_t)(bm + r0) * K + kk);
        cpasync16(sb + soA1,         Ah + (size_t)(bm + r0 + 64) * K + kk);
        cpasync16(sb + A_MAT + soA0, Al + (size_t)(bm + r0) * K + kk);
        cpasync16(sb + A_MAT + soA1, Al + (size_t)(bm + r0 + 64) * K + kk);
        // B (256 rows)
#pragma unroll
        for (int q = 0; q < 4; q++) {
            const uint32_t so = (uint32_t)((r0 + q * 64) * 80 + c0 * 16);
            const size_t gb = (size_t)(bn + r0 + q * 64) * K + kk;
            cpasync16(sb + B_OFF + so,         Bh + gb);
            cpasync16(sb + B_OFF + B_MAT + so, Bl + gb);
        }
        cp_commit();
    };

    float4 acc[4][8];
#pragma unroll
    for (int i = 0; i < 4; i++)
#pragma unroll
        for (int j = 0; j < 8; j++) acc[i][j] = make_float4(0.f, 0.f, 0.f, 0.f);

    // ldmatrix lane addressing
    const int a_row = lane & 15;                 // rows 0..15 within m16
    const int a_kc  = ((lane >> 4) & 1) * 8;     // k 0 or 8
    const int b_row = (lane & 7) + ((lane >> 4) & 1) * 8;  // n row within 16
    const int b_kc  = ((lane >> 3) & 1) * 8;     // k 0 or 8

    const int NT = K / GBK;
    issue_loads(0, 0);
    issue_loads(1, GBK);

    for (int kt = 0; kt < NT; kt++) {
        if (kt + 2 < NT) issue_loads((kt + 2) % 3, (kt + 2) * GBK);
        if (kt + 1 < NT) cp_wait<1>(); else cp_wait<0>();
        __syncthreads();

        const uint32_t st = sbase + (kt % 3) * STAGE_B;
        const uint32_t As_h = st;
        const uint32_t As_l = st + A_MAT;
        const uint32_t Bs_h = st + B_OFF;
        const uint32_t Bs_l = st + B_OFF + B_MAT;

#pragma unroll
        for (int k16 = 0; k16 < 2; k16++) {
            uint32_t ah[4][4], al[4][4];
#pragma unroll
            for (int i = 0; i < 4; i++) {
                const uint32_t ao =
                    (uint32_t)((wm * 64 + i * 16 + a_row) * 80 +
                               (k16 * 16 + a_kc) * 2);
                ldm_x4(ah[i][0], ah[i][1], ah[i][2], ah[i][3], As_h + ao);
                ldm_x4(al[i][0], al[i][1], al[i][2], al[i][3], As_l + ao);
            }
#pragma unroll
            for (int jj = 0; jj < 4; jj++) {     // two n8 tiles per iteration
                const uint32_t bo =
                    (uint32_t)((wn * 64 + jj * 16 + b_row) * 80 +
                               (k16 * 16 + b_kc) * 2);
                uint32_t bh0, bh1, bh2, bh3, bl0, bl1, bl2, bl3;
                ldm_x4(bh0, bh1, bh2, bh3, Bs_h + bo);
                ldm_x4(bl0, bl1, bl2, bl3, Bs_l + bo);
#pragma unroll
                for (int i = 0; i < 4; i++) {
                    mma_bf16(acc[i][jj * 2], ah[i], bh0, bh1);
                    mma_bf16(acc[i][jj * 2], ah[i], bl0, bl1);
                    mma_bf16(acc[i][jj * 2], al[i], bh0, bh1);
                    mma_bf16(acc[i][jj * 2 + 1], ah[i], bh2, bh3);
                    mma_bf16(acc[i][jj * 2 + 1], ah[i], bl2, bl3);
                    mma_bf16(acc[i][jj * 2 + 1], al[i], bh2, bh3);
                }
            }
        }
        __syncthreads();
    }

    // epilogue: warp tile 64x64 at (bm + wm*64, bn + wn*64)
    const int qr = lane >> 2;
    const int qc = (lane & 3) * 2;
#pragma unroll
    for (int i = 0; i < 4; i++) {
#pragma unroll
        for (int j = 0; j < 8; j++) {
            const int gr0 = bm + wm * 64 + i * 16 + qr;
            const int gc  = bn + wn * 64 + j * 8 + qc;
            const float b0 = bias[gc];
            const float b1 = bias[gc + 1];
            float v00 = acc[i][j].x + b0, v01 = acc[i][j].y + b1;
            float v10 = acc[i][j].z + b0, v11 = acc[i][j].w + b1;
            if (ACT == 1) {
                v00 = v00 / (1.0f + expf(-v00));
                v01 = v01 / (1.0f + expf(-v01));
                v10 = v10 / (1.0f + expf(-v10));
                v11 = v11 / (1.0f + expf(-v11));
            }
            if (HAS_ADD) {
                v00 += add[(size_t)gr0 * N + gc];
                v01 += add[(size_t)gr0 * N + gc + 1];
                v10 += add[(size_t)(gr0 + 8) * N + gc];
                v11 += add[(size_t)(gr0 + 8) * N + gc + 1];
            }
            if (SPLIT_OUT) {
                __nv_bfloat16 h00 = __float2bfloat16(v00);
                __nv_bfloat16 h01 = __float2bfloat16(v01);
                __nv_bfloat16 h10 = __float2bfloat16(v10);
                __nv_bfloat16 h11 = __float2bfloat16(v11);
                *reinterpret_cast<__nv_bfloat162*>(Ch + (size_t)gr0 * N + gc) =
                    __nv_bfloat162(h00, h01);
                *reinterpret_cast<__nv_bfloat162*>(Ch + (size_t)(gr0 + 8) * N + gc) =
                    __nv_bfloat162(h10, h11);
                *reinterpret_cast<__nv_bfloat162*>(Cl + (size_t)gr0 * N + gc) =
                    __nv_bfloat162(__float2bfloat16(v00 - __bfloat162float(h00)),
                                   __float2bfloat16(v01 - __bfloat162float(h01)));
                *reinterpret_cast<__nv_bfloat162*>(Cl + (size_t)(gr0 + 8) * N + gc) =
                    __nv_bfloat162(__float2bfloat16(v10 - __bfloat162float(h10)),
                                   __float2bfloat16(v11 - __bfloat162float(h11)));
            } else {
                *reinterpret_cast<float2*>(Cf + (size_t)gr0 * N + gc) =
                    make_float2(v00, v01);
                *reinterpret_cast<float2*>(Cf + (size_t)(gr0 + 8) * N + gc) =
                    make_float2(v10, v11);
            }
        }
    }
}

// ---------------------------------------------------------------------------
// Prep kernels
// ---------------------------------------------------------------------------
__global__ void transpose_split(const float* __restrict__ W,
                                __nv_bfloat16* __restrict__ Th,
                                __nv_bfloat16* __restrict__ Tl, int K, int N) {
    __shared__ float t[32][33];
    const int n0 = blockIdx.x * 32, k0 = blockIdx.y * 32;
    const int tx = threadIdx.x, ty = threadIdx.y;
#pragma unroll
    for (int dy = 0; dy < 32; dy += 8)
        t[ty + dy][tx] = W[(size_t)(k0 + ty + dy) * N + n0 + tx];
    __syncthreads();
#pragma unroll
    for (int dy = 0; dy < 32; dy += 8) {
        const int n = n0 + ty + dy, k = k0 + tx;
        float v = t[tx][ty + dy];
        __nv_bfloat16 h = __float2bfloat16(v);
        Th[(size_t)n * K + k] = h;
        Tl[(size_t)n * K + k] = __float2bfloat16(v - __bfloat162float(h));
    }
}

__global__ void split_f32(const float* __restrict__ x, __nv_bfloat16* __restrict__ h,
                          __nv_bfloat16* __restrict__ l, int n) {
    int i = blockIdx.x * 256 + threadIdx.x;
    if (i < n) {
        float v = x[i];
        __nv_bfloat16 hh = __float2bfloat16(v);
        h[i] = hh;
        l[i] = __float2bfloat16(v - __bfloat162float(hh));
    }
}

__global__ void transpose32f(const float* __restrict__ in, float* __restrict__ out,
                             int R, int C) {
    __shared__ float t[32][33];
    const size_t boff = (size_t)blockIdx.z * R * C;
    const float* ip = in + boff;
    float* op = out + boff;
    const int r0 = blockIdx.y * 32, c0 = blockIdx.x * 32;
    const int tx = threadIdx.x, ty = threadIdx.y;
#pragma unroll
    for (int dy = 0; dy < 32; dy += 8)
        t[ty + dy][tx] = ip[(size_t)(r0 + ty + dy) * C + c0 + tx];
    __syncthreads();
#pragma unroll
    for (int dy = 0; dy < 32; dy += 8)
        op[(size_t)(c0 + ty + dy) * R + r0 + tx] = t[tx][ty + dy];
}

__global__ void init_twd(float2* __restrict__ twd) {
    int k = blockIdx.x * 256 + threadIdx.x;
    if (k < 1024) {
        double s, c;
        sincos(-6.283185307179586476925286766559 * (double)k / 4096.0, &s, &c);
        twd[k] = make_float2((float)c, (float)s);
    }
}

// ---------------------------------------------------------------------------
// Radix-4 4096-point FFT in smem, 256 threads, padded addressing
// ---------------------------------------------------------------------------
#define PIDX(i) ((i) + ((i) >> 4))

__device__ __forceinline__ float2 cmul(float2 a, float2 b) {
    return make_float2(a.x * b.x - a.y * b.y, a.x * b.y + a.y * b.x);
}

template <int SIGN>
__device__ void fft4096_r4(float2* sm, const float2* tw) {
    const int tid = threadIdx.x;
    __syncthreads();
    for (int i = tid; i < NFFT; i += 256) {
        int b = __brev(i) >> 20;
        int r = ((b & 0x555) << 1) | ((b >> 1) & 0x555);
        if (r > i) {
            float2 t = sm[PIDX(i)];
            sm[PIDX(i)] = sm[PIDX(r)];
            sm[PIDX(r)] = t;
        }
    }
    __syncthreads();
#pragma unroll
    for (int st = 0; st < 6; st++) {
        const int len = 4 << (2 * st);
        const int q   = len >> 2;
        const int S   = NFFT / len;
#pragma unroll
        for (int u = 0; u < 4; u++) {
            const int bf = tid + u * 256;
            const int g  = bf / q;
            const int j  = bf - g * q;
            const int base = g * len + j;
            float2 x0 = sm[PIDX(base)];
            float2 x1 = sm[PIDX(base + q)];
            float2 x2 = sm[PIDX(base + 2 * q)];
            float2 x3 = sm[PIDX(base + 3 * q)];
            float2 w1 = tw[j * S];
            if (SIGN > 0) w1.y = -w1.y;
            float2 w2 = cmul(w1, w1);
            float2 w3 = cmul(w1, w2);
            x1 = cmul(x1, w1);
            x2 = cmul(x2, w2);
            x3 = cmul(x3, w3);
            float2 t0 = make_float2(x0.x + x2.x, x0.y + x2.y);
            float2 t1 = make_float2(x0.x - x2.x, x0.y - x2.y);
            float2 t2 = make_float2(x1.x + x3.x, x1.y + x3.y);
            float2 t3 = make_float2(x1.x - x3.x, x1.y - x3.y);
            sm[PIDX(base)]         = make_float2(t0.x + t2.x, t0.y + t2.y);
            sm[PIDX(base + 2 * q)] = make_float2(t0.x - t2.x, t0.y - t2.y);
            if (SIGN < 0) {
                sm[PIDX(base + q)]     = make_float2(t1.x + t3.y, t1.y - t3.x);
                sm[PIDX(base + 3 * q)] = make_float2(t1.x - t3.y, t1.y + t3.x);
            } else {
                sm[PIDX(base + q)]     = make_float2(t1.x - t3.y, t1.y + t3.x);
                sm[PIDX(base + 3 * q)] = make_float2(t1.x + t3.y, t1.y - t3.x);
            }
        }
        __syncthreads();
    }
}

// ---------------------------------------------------------------------------
// Filter spectra: two channels packed per block
// ---------------------------------------------------------------------------
__global__ __launch_bounds__(256)
void filter_fft_packed(const float* __restrict__ hfiltT,
                       const float* __restrict__ a,
                       float2* __restrict__ wfh,
                       const float2* __restrict__ twd) {
    __shared__ float2 sd[PIDX(NFFT)];
    __shared__ float2 tw[1024];
    const int tid = threadIdx.x;
    const int d0 = blockIdx.x * 2;
    const int d1 = d0 + 1;
    for (int i = tid; i < 1024; i += 256) tw[i] = twd[i];
    const float ea = expf(a[0]);
    for (int t = tid; t < LEN; t += 256) {
        const float w = expf(-(float)t * ea);
        sd[PIDX(t)] = make_float2(hfiltT[(size_t)d0 * LEN + t] * w,
                                  hfiltT[(size_t)d1 * LEN + t] * w);
    }
    for (int t = LEN + tid; t < NFFT; t += 256) sd[PIDX(t)] = make_float2(0.f, 0.f);
    fft4096_r4<-1>(sd, tw);
    for (int k = tid; k <= 2048; k += 256) {
        const int i2 = (NFFT - k) & (NFFT - 1);
        float2 X1 = sd[PIDX(k)];
        float2 X2 = sd[PIDX(i2)];
        float2 A = make_float2(0.5f * (X1.x + X2.x), 0.5f * (X1.y - X2.y));
        float2 B = make_float2(0.5f * (X1.y + X2.y), -0.5f * (X1.x - X2.x));
        wfh[(size_t)d0 * WFS + k] = A;
        wfh[(size_t)d1 * WFS + k] = B;
    }
}

// ---------------------------------------------------------------------------
// FFT convolution: two channels per block, coalesced I/O
// ---------------------------------------------------------------------------
__global__ __launch_bounds__(256)
void fftconv_packed(const float* __restrict__ lnzT,
                    const float2* __restrict__ wfh,
                    const float* __restrict__ hidT,
                    float* __restrict__ znewT,
                    const float2* __restrict__ twd) {
    __shared__ float2 sd[PIDX(NFFT)];
    __shared__ float2 tw[1024];
    const int tid = threadIdx.x;
    const int bp = blockIdx.x;
    const int b  = bp >> 9;
    const int d0 = (bp & 511) * 2;
    const int d1 = d0 + 1;
    for (int i = tid; i < 1024; i += 256) tw[i] = twd[i];
    const float* x0 = lnzT + ((size_t)b * DIM + d0) * LEN;
    const float* x1 = lnzT + ((size_t)b * DIM + d1) * LEN;
    for (int t = tid; t < LEN; t += 256)
        sd[PIDX(t)] = make_float2(x0[t], x1[t]);
    for (int t = LEN + tid; t < NFFT; t += 256) sd[PIDX(t)] = make_float2(0.f, 0.f);

    fft4096_r4<-1>(sd, tw);

    const float2* Fa = wfh + (size_t)d0 * WFS;
    const float2* Fb = wfh + (size_t)d1 * WFS;
    for (int k = tid; k <= 2048; k += 256) {
        const int i2 = (NFFT - k) & (NFFT - 1);
        float2 X1 = sd[PIDX(k)];
        float2 X2 = sd[PIDX(i2)];
        float2 A = make_float2(0.5f * (X1.x + X2.x), 0.5f * (X1.y - X2.y));
        float2 B = make_float2(0.5f * (X1.y + X2.y), -0.5f * (X1.x - X2.x));
        float2 Ya = cmul(A, Fa[k]);
        float2 Yb = cmul(B, Fb[k]);
        sd[PIDX(k)] = make_float2(Ya.x - Yb.y, Ya.y + Yb.x);
        if (k != 0 && k != 2048)
            sd[PIDX(i2)] = make_float2(Ya.x + Yb.y, Yb.x - Ya.y);
    }

    fft4096_r4<1>(sd, tw);

    const float inv = 1.0f / (float)NFFT;
    float* o0 = znewT + ((size_t)b * DIM + d0) * LEN;
    float* o1 = znewT + ((size_t)b * DIM + d1) * LEN;
    const float* h0 = hidT + (size_t)d0 * LEN;
    const float* h1 = hidT + (size_t)d1 * LEN;
    for (int t = tid; t < LEN; t += 256) {
        float2 v = sd[PIDX(t)];
        o0[t] = v.x * inv + h0[t];
        o1[t] = v.y * inv + h1[t];
    }
}

// ---------------------------------------------------------------------------
// LayerNorm kernels
// ---------------------------------------------------------------------------
__global__ void layernorm_rows(const float* __restrict__ x,
                               const float* __restrict__ gvec,
                               const float* __restrict__ bvec,
                               float* __restrict__ y) {
    const int row = blockIdx.x;
    const int tid = threadIdx.x;
    const float4 v = reinterpret_cast<const float4*>(x + (size_t)row * DIM)[tid];
    float s  = v.x + v.y + v.z + v.w;
    float s2 = v.x * v.x + v.y * v.y + v.z * v.z + v.w * v.w;
    __shared__ float rs[256], rs2[256];
    rs[tid] = s; rs2[tid] = s2;
    __syncthreads();
    for (int o = 128; o > 0; o >>= 1) {
        if (tid < o) { rs[tid] += rs[tid + o]; rs2[tid] += rs2[tid + o]; }
        __syncthreads();
    }
    const float mean = rs[0] * (1.0f / DIM);
    const float var  = rs2[0] * (1.0f / DIM) - mean * mean;
    const float rstd = rsqrtf(var + LN_EPS);
    const float4 gg = reinterpret_cast<const float4*>(gvec)[tid];
    const float4 bb = reinterpret_cast<const float4*>(bvec)[tid];
    float4 o;
    o.x = (v.x - mean) * rstd * gg.x + bb.x;
    o.y = (v.y - mean) * rstd * gg.y + bb.y;
    o.z = (v.z - mean) * rstd * gg.z + bb.z;
    o.w = (v.w - mean) * rstd * gg.w + bb.w;
    reinterpret_cast<float4*>(y + (size_t)row * DIM)[tid] = o;
}

__global__ void layernorm_rows_split(const float* __restrict__ x,
                                     const float* __restrict__ gvec,
                                     const float* __restrict__ bvec,
                                     __nv_bfloat16* __restrict__ yh,
                                     __nv_bfloat16* __restrict__ yl) {
    const int row = blockIdx.x;
    const int tid = threadIdx.x;
    const float4 v = reinterpret_cast<const float4*>(x + (size_t)row * DIM)[tid];
    float s  = v.x + v.y + v.z + v.w;
    float s2 = v.x * v.x + v.y * v.y + v.z * v.z + v.w * v.w;
    __shared__ float rs[256], rs2[256];
    rs[tid] = s; rs2[tid] = s2;
    __syncthreads();
    for (int o = 128; o > 0; o >>= 1) {
        if (tid < o) { rs[tid] += rs[tid + o]; rs2[tid] += rs2[tid + o]; }
        __syncthreads();
    }
    const float mean = rs[0] * (1.0f / DIM);
    const float var  = rs2[0] * (1.0f / DIM) - mean * mean;
    const float rstd = rsqrtf(var + LN_EPS);
    const float4 gg = reinterpret_cast<const float4*>(gvec)[tid];
    const float4 bb = reinterpret_cast<const float4*>(bvec)[tid];
    float o[4];
    o[0] = (v.x - mean) * rstd * gg.x + bb.x;
    o[1] = (v.y - mean) * rstd * gg.y + bb.y;
    o[2] = (v.z - mean) * rstd * gg.z + bb.z;
    o[3] = (v.w - mean) * rstd * gg.w + bb.w;
    __nv_bfloat16 hh[4], ll[4];
#pragma unroll
    for (int j = 0; j < 4; j++) {
        hh[j] = __float2bfloat16(o[j]);
        ll[j] = __float2bfloat16(o[j] - __bfloat162float(hh[j]));
    }
    const size_t base = (size_t)row * DIM + tid * 4;
    *reinterpret_cast<ushort4*>(yh + base) = *reinterpret_cast<ushort4*>(hh);
    *reinterpret_cast<ushort4*>(yl + base) = *reinterpret_cast<ushort4*>(ll);
}

// ---------------------------------------------------------------------------
// Launch
// ---------------------------------------------------------------------------
extern "C" void kernel_launch(void* const* d_in, const int* in_sizes, int n_in,
                              void* d_out, int out_size) {
    const float* z      = (const float*)d_in[0];
    const float* pos    = (const float*)d_in[1];
    const float* a      = (const float*)d_in[2];
    const float* hidden = (const float*)d_in[3];
    const float* ln_g   = (const float*)d_in[4];
    const float* ln_b   = (const float*)d_in[5];
    const float* wp1    = (const float*)d_in[6];
    const float* bp1    = (const float*)d_in[7];
    const float* wp2    = (const float*)d_in[8];
    const float* bp2    = (const float*)d_in[9];
    const float* w1     = (const float*)d_in[10];
    const float* b1     = (const float*)d_in[11];
    const float* w2     = (const float*)d_in[12];
    const float* b2     = (const float*)d_in[13];
    float* out = (float*)d_out;

    float *lnz, *lnzT, *hfilt, *hfiltT, *hidT, *znewT, *znew;
    float2 *wfh, *twd;
    __nv_bfloat16 *Xh, *Xl, *Hh, *Hl, *posh, *posl;
    __nv_bfloat16 *wp1t_h, *wp1t_l, *wp2t_h, *wp2t_l, *w1t_h, *w1t_l, *w2t_h, *w2t_l;
    cudaGetSymbolAddress((void**)&lnz,    g_lnz);
    cudaGetSymbolAddress((void**)&lnzT,   g_lnzT);
    cudaGetSymbolAddress((void**)&hfilt,  g_hfilt);
    cudaGetSymbolAddress((void**)&hfiltT, g_hfiltT);
    cudaGetSymbolAddress((void**)&hidT,   g_hidT);
    cudaGetSymbolAddress((void**)&wfh,    g_wfh);
    cudaGetSymbolAddress((void**)&twd,    g_twd);
    cudaGetSymbolAddress((void**)&znewT,  g_znewT);
    cudaGetSymbolAddress((void**)&znew,   g_znew);
    cudaGetSymbolAddress((void**)&Xh,     g_Xh);
    cudaGetSymbolAddress((void**)&Xl,     g_Xl);
    cudaGetSymbolAddress((void**)&Hh,     g_Hh);
    cudaGetSymbolAddress((void**)&Hl,     g_Hl);
    cudaGetSymbolAddress((void**)&posh,   g_posh);
    cudaGetSymbolAddress((void**)&posl,   g_posl);
    cudaGetSymbolAddress((void**)&wp1t_h, g_wp1t_h);
    cudaGetSymbolAddress((void**)&wp1t_l, g_wp1t_l);
    cudaGetSymbolAddress((void**)&wp2t_h, g_wp2t_h);
    cudaGetSymbolAddress((void**)&wp2t_l, g_wp2t_l);
    cudaGetSymbolAddress((void**)&w1t_h,  g_w1t_h);
    cudaGetSymbolAddress((void**)&w1t_l,  g_w1t_l);
    cudaGetSymbolAddress((void**)&w2t_h,  g_w2t_h);
    cudaGetSymbolAddress((void**)&w2t_l,  g_w2t_l);

    cudaFuncSetAttribute(gemm_mma<1, true,  false>,
                         cudaFuncAttributeMaxDynamicSharedMemorySize, GEMM_SMEM);
    cudaFuncSetAttribute(gemm_mma<0, false, false>,
                         cudaFuncAttributeMaxDynamicSharedMemorySize, GEMM_SMEM);
    cudaFuncSetAttribute(gemm_mma<0, false, true>,
                         cudaFuncAttributeMaxDynamicSharedMemorySize, GEMM_SMEM);

    // 0) prep
    transpose_split<<<dim3(DFF / 32, DIM / 32), dim3(32, 8)>>>(wp1, wp1t_h, wp1t_l, DIM, DFF);
    transpose_split<<<dim3(DIM / 32, DFF / 32), dim3(32, 8)>>>(wp2, wp2t_h, wp2t_l, DFF, DIM);
    transpose_split<<<dim3(DFF / 32, DIM / 32), dim3(32, 8)>>>(w1,  w1t_h,  w1t_l,  DIM, DFF);
    transpose_split<<<dim3(DIM / 32, DFF / 32), dim3(32, 8)>>>(w2,  w2t_h,  w2t_l,  DFF, DIM);
    split_f32<<<(LEN * DIM + 255) / 256, 256>>>(pos, posh, posl, LEN * DIM);
    init_twd<<<4, 256>>>(twd);
    transpose32f<<<dim3(DIM / 32, LEN / 32, 1), dim3(32, 8)>>>(hidden, hidT, LEN, DIM);

    // 1) filter FFN
    gemm_mma<1, true, false><<<dim3(DFF / GBN, LEN / GBM), 256, GEMM_SMEM>>>(
        posh, posl, wp1t_h, wp1t_l, bp1, nullptr, nullptr, Hh, Hl, LEN, DFF, DIM);
    gemm_mma<0, false, false><<<dim3(DIM / GBN, LEN / GBM), 256, GEMM_SMEM>>>(
        Hh, Hl, wp2t_h, wp2t_l, bp2, nullptr, hfilt, nullptr, nullptr, LEN, DIM, DFF);
    transpose32f<<<dim3(DIM / 32, LEN / 32, 1), dim3(32, 8)>>>(hfilt, hfiltT, LEN, DIM);

    // 2) filter spectra
    filter_fft_packed<<<DIM / 2, 256>>>(hfiltT, a, wfh, twd);

    // 3) LN(z) + transpose
    layernorm_rows<<<BATCH * LEN, 256>>>(z, ln_g, ln_b, lnz);
    transpose32f<<<dim3(DIM / 32, LEN / 32, BATCH), dim3(32, 8)>>>(lnz, lnzT, LEN, DIM);

    // 4) FFT convolution + hidden residual
    fftconv_packed<<<BATCH * DIM / 2, 256>>>(lnzT, wfh, hidT, znewT, twd);
    transpose32f<<<dim3(LEN / 32, DIM / 32, BATCH), dim3(32, 8)>>>(znewT, znew, DIM, LEN);

    // 5) LN(znew) -> split bf16
    layernorm_rows_split<<<BATCH * LEN, 256>>>(znew, ln_g, ln_b, Xh, Xl);

    // 6) main FFN + residual
    gemm_mma<1, true, false><<<dim3(DFF / GBN, (BATCH * LEN) / GBM), 256, GEMM_SMEM>>>(
        Xh, Xl, w1t_h, w1t_l, b1, nullptr, nullptr, Hh, Hl, BATCH * LEN, DFF, DIM);
    gemm_mma<0, false, true><<<dim3(DIM / GBN, (BATCH * LEN) / GBM), 256, GEMM_SMEM>>>(
        Hh, Hl, w2t_h, w2t_l, b2, znew, out, nullptr, nullptr, BATCH * LEN, DIM, DFF);
}